// round 13
// baseline (speedup 1.0000x reference)
#include <cuda_runtime.h>
#include <cuda_bf16.h>
#include <cstddef>

// RandCropResize: R12 rolling-window staging + pair-per-thread main phase.
// Main phase: thread t -> (row = t>>8, pixel pair = t&255); one pair-packed
// int4 x-tap load, 12 LDS, 12 FFMA, 3 plain float2 stores (STG.64 at 7.75
// issue-cycles replaces 2x STG.32 at 5 each). Staging unchanged from R12:
// 1-3-row rolling register window, fused y-lerp, double buffer, one
// __syncthreads per 2-row group.

#define IMG_H 512
#define IMG_W 512
#define IMG_C 3
#define RPI   2               // rows per pipeline iteration
#define NITER 8               // iterations per block -> 16 rows/block
#define SPITCH 520            // smem row pitch (floats), float4-aligned

__device__ int4 g_xtab[64 * (IMG_W / 2)];   // per pair: {l0a|l1a<<16, wxa, l0b|l1b<<16, wxb}
__device__ int2 g_ytab[64 * IMG_H];

__device__ __forceinline__ void x_taps(int w, int X1, int X2, int xlo,
                                       int& packed, float& wx)
{
    const int   ncx = X2 - X1;
    const float nx  = (float)ncx;
    float sx = ((float)w + 0.5f) * nx * (1.0f / (float)IMG_W) - 0.5f;
    sx = fminf(fmaxf(sx, 0.0f), nx - 1.0f);
    const int ix0 = (int)floorf(sx);
    const int ix1 = min(ix0 + 1, ncx - 1);
    wx = sx - (float)ix0;
    packed = ((X1 + ix0) - xlo) | (((X1 + ix1) - xlo) << 16);
}

__global__ void __launch_bounds__(512)
setup_tables_kernel(const int* __restrict__ y1v, const int* __restrict__ y2v,
                    const int* __restrict__ x1v, const int* __restrict__ x2v)
{
    const int b = blockIdx.x;
    const int t = threadIdx.x;

    const int Y1 = y1v[b], Y2 = y2v[b];
    const int X1 = x1v[b], X2 = x2v[b];

    {   // y taps for h = t (absolute source rows)
        const int   ncy = Y2 - Y1;
        const float ny  = (float)ncy;
        float sy = ((float)t + 0.5f) * ny * (1.0f / (float)IMG_H) - 0.5f;
        sy = fminf(fmaxf(sy, 0.0f), ny - 1.0f);
        const int   iy0 = (int)floorf(sy);
        const int   iy1 = min(iy0 + 1, ncy - 1);
        const float wy  = sy - (float)iy0;
        int2 e;
        e.x = (Y1 + iy0) | ((Y1 + iy1) << 16);
        e.y = __float_as_int(wy);
        g_ytab[(b << 9) + t] = e;
    }
    if (t < (IMG_W / 2)) {     // x taps for pixel pair t (smem-relative)
        const int xlo = X1 & ~3;
        int   pa, pb;
        float wxa, wxb;
        x_taps(2 * t,     X1, X2, xlo, pa, wxa);
        x_taps(2 * t + 1, X1, X2, xlo, pb, wxb);
        int4 e;
        e.x = pa;
        e.y = __float_as_int(wxa);
        e.z = pb;
        e.w = __float_as_int(wxb);
        g_xtab[b * (IMG_W / 2) + t] = e;
    }
}

__device__ __forceinline__ float4 lerp4(float4 a, float4 b, float w)
{
    float4 f;
    f.x = a.x + (b.x - a.x) * w;
    f.y = a.y + (b.y - a.y) * w;
    f.z = a.z + (b.z - a.z) * w;
    f.w = a.w + (b.w - a.w) * w;
    return f;
}

__global__ void __launch_bounds__(512, 4)
rand_crop_resize_kernel(const float* __restrict__ img,
                        const int* __restrict__ x1v,
                        const int* __restrict__ x2v,
                        float* __restrict__ out)
{
    __shared__ float sbuf[2][RPI * IMG_C * SPITCH];   // 2 x 12.2 KB

    const int hchunk = blockIdx.x * (RPI * NITER);    // 16 rows per block
    const int b      = blockIdx.y;
    const int tid    = threadIdx.x;

    const int X1    = x1v[b];
    const int X2    = x2v[b];
    const int xlo   = X1 & ~3;
    const int span4 = (((X2 + 3) & ~3) - xlo) >> 2;   // <= 128

    const size_t img_stride = (size_t)IMG_H * IMG_W;
    const float* base = img + (size_t)b * IMG_C * img_stride;

    // main-phase identity: one row of the group, two adjacent pixels
    const int   rmain = tid >> 8;             // 0 or 1
    const int   pair  = tid & 255;
    const int4  xe  = __ldg(&g_xtab[b * (IMG_W / 2) + pair]);
    const int   l0a = xe.x & 0xFFFF;
    const int   l1a = xe.x >> 16;
    const float wxa = __int_as_float(xe.y);
    const int   l0b = xe.z & 0xFFFF;
    const int   l1b = xe.z >> 16;
    const float wxb = __int_as_float(xe.w);

    // staging role (fixed per thread)
    const int  ns     = IMG_C * span4;                // <= 384
    const bool active = tid < ns;
    const int  c      = (tid >= span4) + (tid >= 2 * span4);
    const int  xq     = tid - c * span4;
    const float* pc   = base + (size_t)c * img_stride + xlo + (xq << 2);

    // rolling window: rows rb .. rb+hi held in v0..v2 (hi <= 2)
    float4 v0, v1, v2;
    int    rb, hi;
    int    d1, d2, d3;
    float  wy0, wy1;

    // ---- prologue: load window for group 0 ----
    {
        const int2 ye0 = __ldg(&g_ytab[(b << 9) + hchunk]);
        const int2 ye1 = __ldg(&g_ytab[(b << 9) + hchunk + 1]);
        rb  = ye0.x & 0xFFFF;
        d1  = (ye0.x >> 16) - rb;
        d2  = (ye1.x & 0xFFFF) - rb;
        d3  = (ye1.x >> 16) - rb;
        wy0 = __int_as_float(ye0.y);
        wy1 = __int_as_float(ye1.y);
        v0 = v1 = v2 = make_float4(0.f, 0.f, 0.f, 0.f);
        if (active) {
            v0 = *(const float4*)(pc + (size_t)rb * IMG_W);
            if (d3 >= 1) v1 = *(const float4*)(pc + (size_t)(rb + 1) * IMG_W);
            if (d3 >= 2) v2 = *(const float4*)(pc + (size_t)(rb + 2) * IMG_W);
        }
        hi = d3;
    }

    float* const oblk = out + (size_t)b * IMG_C * img_stride
                            + (size_t)(hchunk + rmain) * IMG_W + (pair << 1);

    for (int g = 0; g < NITER; g++) {
        const int p = g & 1;

        // ---- STS: y-lerp the two output rows from the window ----
        if (active) {
            const float4 r0b = d1 ? v1 : v0;
            *(float4*)(&sbuf[p][(0 * IMG_C + c) * SPITCH + (xq << 2)]) =
                lerp4(v0, r0b, wy0);
            const float4 r1a = d2 ? v1 : v0;
            const float4 r1b = (d3 == 0) ? v0 : ((d3 == 1) ? v1 : v2);
            *(float4*)(&sbuf[p][(1 * IMG_C + c) * SPITCH + (xq << 2)]) =
                lerp4(r1a, r1b, wy1);
        }

        // ---- advance rolling window to group g+1 ----
        if (g + 1 < NITER) {
            const int  hn  = hchunk + (g + 1) * RPI;
            const int2 ye0 = __ldg(&g_ytab[(b << 9) + hn]);
            const int2 ye1 = __ldg(&g_ytab[(b << 9) + hn + 1]);
            const int  nrb = ye0.x & 0xFFFF;
            d1  = (ye0.x >> 16) - nrb;
            d2  = (ye1.x & 0xFFFF) - nrb;
            d3  = (ye1.x >> 16) - nrb;
            wy0 = __int_as_float(ye0.y);
            wy1 = __int_as_float(ye1.y);

            const int shift = nrb - rb;       // 0..2, block-uniform
            if (shift == 1)      { v0 = v1; v1 = v2; }
            else if (shift == 2) { v0 = v2; }
            const int valid = hi - shift;
            if (active) {
                if (valid < 0)            v0 = *(const float4*)(pc + (size_t)nrb * IMG_W);
                if (valid < 1 && d3 >= 1) v1 = *(const float4*)(pc + (size_t)(nrb + 1) * IMG_W);
                if (valid < 2 && d3 >= 2) v2 = *(const float4*)(pc + (size_t)(nrb + 2) * IMG_W);
            }
            hi = (d3 > valid) ? d3 : valid;
            rb = nrb;
        }

        __syncthreads();   // one barrier per group

        // ---- main: this thread's row, 2 pixels x 3 channels, STG.64 ----
        const float* sb = &sbuf[p][rmain * IMG_C * SPITCH];
        float* og = oblk + (size_t)(g * RPI) * IMG_W;
#pragma unroll
        for (int cc = 0; cc < IMG_C; cc++) {
            const float* s = sb + cc * SPITCH;
            const float f0a = s[l0a];
            const float f1a = s[l1a];
            const float f0b = s[l0b];
            const float f1b = s[l1b];
            float2 o;
            o.x = f0a + (f1a - f0a) * wxa;
            o.y = f0b + (f1b - f0b) * wxb;
            *(float2*)(og + (size_t)cc * img_stride) = o;
        }
    }
}

extern "C" void kernel_launch(void* const* d_in, const int* in_sizes, int n_in,
                              void* d_out, int out_size)
{
    const float* img = (const float*)d_in[0];
    const int*   y1  = (const int*)d_in[1];
    const int*   y2  = (const int*)d_in[2];
    const int*   x1  = (const int*)d_in[3];
    const int*   x2  = (const int*)d_in[4];
    float*       out = (float*)d_out;

    setup_tables_kernel<<<64, 512>>>(y1, y2, x1, x2);

    dim3 grid(IMG_H / (RPI * NITER), 64);   // (row chunk, b) = (32, 64)
    dim3 block(512);
    rand_crop_resize_kernel<<<grid, block>>>(img, x1, x2, out);
}

// round 15
// speedup vs baseline: 1.1455x; 1.1455x over previous
#include <cuda_runtime.h>
#include <cuda_bf16.h>
#include <cstddef>

// RandCropResize: R12 (rolling-window staging, double buffer, 1-pixel main
// phase) with: 32 rows per block (NITER=16) to amortize prologue and keep
// windows rolling longer; simplified window bookkeeping (hi == d3 invariant);
// next group's y-table entries loaded into raw temps at loop top (earlier
// LDG issue, no WAR); unroll 2 so the buffer parity is static.

#define IMG_H 512
#define IMG_W 512
#define IMG_C 3
#define RPI   2               // rows per pipeline iteration
#define NITER 16              // iterations per block -> 32 rows/block
#define SPITCH 520            // smem row pitch (floats), float4-aligned

__device__ int2 g_xtab[64 * IMG_W];
__device__ int2 g_ytab[64 * IMG_H];

__global__ void __launch_bounds__(512)
setup_tables_kernel(const int* __restrict__ y1v, const int* __restrict__ y2v,
                    const int* __restrict__ x1v, const int* __restrict__ x2v)
{
    const int b = blockIdx.x;
    const int t = threadIdx.x;

    const int Y1 = y1v[b], Y2 = y2v[b];
    const int X1 = x1v[b], X2 = x2v[b];

    {   // y taps for h = t (absolute source rows)
        const int   ncy = Y2 - Y1;
        const float ny  = (float)ncy;
        float sy = ((float)t + 0.5f) * ny * (1.0f / (float)IMG_H) - 0.5f;
        sy = fminf(fmaxf(sy, 0.0f), ny - 1.0f);
        const int   iy0 = (int)floorf(sy);
        const int   iy1 = min(iy0 + 1, ncy - 1);
        const float wy  = sy - (float)iy0;
        int2 e;
        e.x = (Y1 + iy0) | ((Y1 + iy1) << 16);
        e.y = __float_as_int(wy);
        g_ytab[(b << 9) + t] = e;
    }
    {   // x taps for w = t (smem-relative: minus xlo)
        const int   xlo = X1 & ~3;
        const int   ncx = X2 - X1;
        const float nx  = (float)ncx;
        float sx = ((float)t + 0.5f) * nx * (1.0f / (float)IMG_W) - 0.5f;
        sx = fminf(fmaxf(sx, 0.0f), nx - 1.0f);
        const int   ix0 = (int)floorf(sx);
        const int   ix1 = min(ix0 + 1, ncx - 1);
        const float wx  = sx - (float)ix0;
        int2 e;
        e.x = ((X1 + ix0) - xlo) | (((X1 + ix1) - xlo) << 16);
        e.y = __float_as_int(wx);
        g_xtab[(b << 9) + t] = e;
    }
}

__device__ __forceinline__ float4 lerp4(float4 a, float4 b, float w)
{
    float4 f;
    f.x = a.x + (b.x - a.x) * w;
    f.y = a.y + (b.y - a.y) * w;
    f.z = a.z + (b.z - a.z) * w;
    f.w = a.w + (b.w - a.w) * w;
    return f;
}

__global__ void __launch_bounds__(512, 4)
rand_crop_resize_kernel(const float* __restrict__ img,
                        const int* __restrict__ x1v,
                        const int* __restrict__ x2v,
                        float* __restrict__ out)
{
    __shared__ float sbuf[2][RPI * IMG_C * SPITCH];   // 2 x 12.2 KB

    const int hchunk = blockIdx.x * (RPI * NITER);    // 32 rows per block
    const int b      = blockIdx.y;
    const int tid    = threadIdx.x;

    const int X1    = __ldg(&x1v[b]);
    const int X2    = __ldg(&x2v[b]);
    const int xlo   = X1 & ~3;
    const int span4 = (((X2 + 3) & ~3) - xlo) >> 2;   // <= 128

    const size_t img_stride = (size_t)IMG_H * IMG_W;
    const float* base = img + (size_t)b * IMG_C * img_stride;

    // x taps: once per thread, reused for all rows
    const int2  xe = __ldg(&g_xtab[(b << 9) + tid]);
    const int   l0 = xe.x & 0xFFFF;
    const int   l1 = xe.x >> 16;
    const float wx = __int_as_float(xe.y);

    // staging role (fixed per thread)
    const int  ns     = IMG_C * span4;                // <= 384
    const bool active = tid < ns;
    const int  c      = (tid >= span4) + (tid >= 2 * span4);
    const int  xq     = tid - c * span4;
    const float* pc   = base + (size_t)c * img_stride + xlo + (xq << 2);

    // rolling window: rows rb .. rb+d3 held in v0..v2 (d3 <= 2)
    float4 v0, v1, v2;
    int    rb;
    int    d1, d2, d3;
    float  wy0, wy1;

    // ---- prologue: load window for group 0 ----
    {
        const int2 ye0 = __ldg(&g_ytab[(b << 9) + hchunk]);
        const int2 ye1 = __ldg(&g_ytab[(b << 9) + hchunk + 1]);
        rb  = ye0.x & 0xFFFF;
        d1  = (ye0.x >> 16) - rb;
        d2  = (ye1.x & 0xFFFF) - rb;
        d3  = (ye1.x >> 16) - rb;
        wy0 = __int_as_float(ye0.y);
        wy1 = __int_as_float(ye1.y);
        v0 = v1 = v2 = make_float4(0.f, 0.f, 0.f, 0.f);
        if (active) {
            v0 = *(const float4*)(pc + (size_t)rb * IMG_W);
            if (d3 >= 1) v1 = *(const float4*)(pc + (size_t)(rb + 1) * IMG_W);
            if (d3 >= 2) v2 = *(const float4*)(pc + (size_t)(rb + 2) * IMG_W);
        }
    }

    float* const oblk = out + (size_t)b * IMG_C * img_stride
                            + (size_t)hchunk * IMG_W + tid;

#pragma unroll 2
    for (int g = 0; g < NITER; g++) {
        const int p = g & 1;

        // ---- early issue: next group's y-table loads (raw temps, no WAR) ----
        int2 tye0, tye1;
        if (g + 1 < NITER) {
            const int hn = hchunk + (g + 1) * RPI;
            tye0 = __ldg(&g_ytab[(b << 9) + hn]);
            tye1 = __ldg(&g_ytab[(b << 9) + hn + 1]);
        }

        // ---- STS: y-lerp the two output rows from the window ----
        if (active) {
            const float4 r0b = d1 ? v1 : v0;
            *(float4*)(&sbuf[p][(0 * IMG_C + c) * SPITCH + (xq << 2)]) =
                lerp4(v0, r0b, wy0);
            const float4 r1a = d2 ? v1 : v0;
            const float4 r1b = (d3 == 0) ? v0 : ((d3 == 1) ? v1 : v2);
            *(float4*)(&sbuf[p][(1 * IMG_C + c) * SPITCH + (xq << 2)]) =
                lerp4(r1a, r1b, wy1);
        }

        // ---- advance rolling window to group g+1 ----
        if (g + 1 < NITER) {
            const int nrb = tye0.x & 0xFFFF;
            const int shift = nrb - rb;       // 0..2, block-uniform
            const int valid = d3 - shift;     // highest still-valid idx (hi == d3)
            d1  = (tye0.x >> 16) - nrb;
            d2  = (tye1.x & 0xFFFF) - nrb;
            d3  = (tye1.x >> 16) - nrb;
            wy0 = __int_as_float(tye0.y);
            wy1 = __int_as_float(tye1.y);

            if (shift == 1)      { v0 = v1; v1 = v2; }
            else if (shift == 2) { v0 = v2; }
            if (active) {
                if (valid < 0)            v0 = *(const float4*)(pc + (size_t)nrb * IMG_W);
                if (valid < 1 && d3 >= 1) v1 = *(const float4*)(pc + (size_t)(nrb + 1) * IMG_W);
                if (valid < 2 && d3 >= 2) v2 = *(const float4*)(pc + (size_t)(nrb + 2) * IMG_W);
            }
            rb = nrb;
        }

        __syncthreads();   // one barrier per group

        // ---- main: horizontal lerp, 2 LDS + 2 FFMA + 1 STG per output ----
        float* og = oblk + (size_t)(g * RPI) * IMG_W;
#pragma unroll
        for (int r = 0; r < RPI; r++) {
#pragma unroll
            for (int cc = 0; cc < IMG_C; cc++) {
                const float f0 = sbuf[p][(r * IMG_C + cc) * SPITCH + l0];
                const float f1 = sbuf[p][(r * IMG_C + cc) * SPITCH + l1];
                og[(size_t)cc * img_stride + (size_t)r * IMG_W] =
                    f0 + (f1 - f0) * wx;
            }
        }
    }
}

extern "C" void kernel_launch(void* const* d_in, const int* in_sizes, int n_in,
                              void* d_out, int out_size)
{
    const float* img = (const float*)d_in[0];
    const int*   y1  = (const int*)d_in[1];
    const int*   y2  = (const int*)d_in[2];
    const int*   x1  = (const int*)d_in[3];
    const int*   x2  = (const int*)d_in[4];
    float*       out = (float*)d_out;

    setup_tables_kernel<<<64, 512>>>(y1, y2, x1, x2);

    dim3 grid(IMG_H / (RPI * NITER), 64);   // (row chunk, b) = (16, 64)
    dim3 block(512);
    rand_crop_resize_kernel<<<grid, block>>>(img, x1, x2, out);
}

// round 16
// speedup vs baseline: 1.1538x; 1.0072x over previous
#include <cuda_runtime.h>
#include <cuda_bf16.h>
#include <cstddef>

// RandCropResize: single fused kernel. Rolling-window staging with fused
// y-lerp, double-buffered smem, one barrier per 2-row group, 1-pixel/thread
// stride-1 main phase. Tap tables are gone: x-taps computed inline once per
// thread; the block's 16 y-tap entries computed by threads 0-15 into smem in
// the prologue (in-loop y reads are 29-cyc LDS broadcasts).

#define IMG_H 512
#define IMG_W 512
#define IMG_C 3
#define RPI   2               // rows per pipeline iteration
#define NITER 8               // iterations per block -> 16 rows/block
#define NROWS (RPI * NITER)
#define SPITCH 520            // smem row pitch (floats), float4-aligned

__device__ __forceinline__ float4 lerp4(float4 a, float4 b, float w)
{
    float4 f;
    f.x = a.x + (b.x - a.x) * w;
    f.y = a.y + (b.y - a.y) * w;
    f.z = a.z + (b.z - a.z) * w;
    f.w = a.w + (b.w - a.w) * w;
    return f;
}

__global__ void __launch_bounds__(512, 4)
rand_crop_resize_kernel(const float* __restrict__ img,
                        const int* __restrict__ y1v,
                        const int* __restrict__ y2v,
                        const int* __restrict__ x1v,
                        const int* __restrict__ x2v,
                        float* __restrict__ out)
{
    __shared__ float sbuf[2][RPI * IMG_C * SPITCH];   // 2 x 12.2 KB
    __shared__ int2  s_ytab[NROWS];                   // this block's y taps

    const int hchunk = blockIdx.x * NROWS;            // 16 rows per block
    const int b      = blockIdx.y;
    const int tid    = threadIdx.x;

    const int X1    = __ldg(&x1v[b]);
    const int X2    = __ldg(&x2v[b]);
    const int xlo   = X1 & ~3;
    const int span4 = (((X2 + 3) & ~3) - xlo) >> 2;   // <= 128

    // ---- inline x taps: once per thread, amortized over 16 rows ----
    int   l0, l1;
    float wx;
    {
        const int   ncx = X2 - X1;
        const float nx  = (float)ncx;
        float sx = ((float)tid + 0.5f) * nx * (1.0f / (float)IMG_W) - 0.5f;
        sx = fminf(fmaxf(sx, 0.0f), nx - 1.0f);
        const int ix0 = (int)floorf(sx);
        const int ix1 = min(ix0 + 1, ncx - 1);
        wx = sx - (float)ix0;
        l0 = (X1 + ix0) - xlo;
        l1 = (X1 + ix1) - xlo;
    }

    // ---- y taps for this block's 16 rows: threads 0-15 -> smem ----
    if (tid < NROWS) {
        const int   Y1  = __ldg(&y1v[b]);
        const int   Y2  = __ldg(&y2v[b]);
        const int   ncy = Y2 - Y1;
        const float ny  = (float)ncy;
        float sy = ((float)(hchunk + tid) + 0.5f) * ny * (1.0f / (float)IMG_H)
                 - 0.5f;
        sy = fminf(fmaxf(sy, 0.0f), ny - 1.0f);
        const int   iy0 = (int)floorf(sy);
        const int   iy1 = min(iy0 + 1, ncy - 1);
        const float wy  = sy - (float)iy0;
        int2 e;
        e.x = (Y1 + iy0) | ((Y1 + iy1) << 16);
        e.y = __float_as_int(wy);
        s_ytab[tid] = e;
    }

    const size_t img_stride = (size_t)IMG_H * IMG_W;
    const float* base = img + (size_t)b * IMG_C * img_stride;

    // staging role (fixed per thread)
    const int  ns     = IMG_C * span4;                // <= 384
    const bool active = tid < ns;
    const int  c      = (tid >= span4) + (tid >= 2 * span4);
    const int  xq     = tid - c * span4;
    const float* pc   = base + (size_t)c * img_stride + xlo + (xq << 2);

    __syncthreads();   // s_ytab ready

    // rolling window: rows rb .. rb+d3 held in v0..v2 (d3 <= 2)
    float4 v0, v1, v2;
    int    rb;
    int    d1, d2, d3;
    float  wy0, wy1;

    // ---- prologue: load window for group 0 ----
    {
        const int2 ye0 = s_ytab[0];
        const int2 ye1 = s_ytab[1];
        rb  = ye0.x & 0xFFFF;
        d1  = (ye0.x >> 16) - rb;
        d2  = (ye1.x & 0xFFFF) - rb;
        d3  = (ye1.x >> 16) - rb;
        wy0 = __int_as_float(ye0.y);
        wy1 = __int_as_float(ye1.y);
        v0 = v1 = v2 = make_float4(0.f, 0.f, 0.f, 0.f);
        if (active) {
            v0 = *(const float4*)(pc + (size_t)rb * IMG_W);
            if (d3 >= 1) v1 = *(const float4*)(pc + (size_t)(rb + 1) * IMG_W);
            if (d3 >= 2) v2 = *(const float4*)(pc + (size_t)(rb + 2) * IMG_W);
        }
    }

    float* const oblk = out + (size_t)b * IMG_C * img_stride
                            + (size_t)hchunk * IMG_W + tid;

#pragma unroll 2
    for (int g = 0; g < NITER; g++) {
        const int p = g & 1;

        // ---- next group's y taps (cheap LDS broadcast, no WAR) ----
        int2 tye0, tye1;
        if (g + 1 < NITER) {
            tye0 = s_ytab[(g + 1) * RPI];
            tye1 = s_ytab[(g + 1) * RPI + 1];
        }

        // ---- STS: y-lerp the two output rows from the window ----
        if (active) {
            const float4 r0b = d1 ? v1 : v0;
            *(float4*)(&sbuf[p][(0 * IMG_C + c) * SPITCH + (xq << 2)]) =
                lerp4(v0, r0b, wy0);
            const float4 r1a = d2 ? v1 : v0;
            const float4 r1b = (d3 == 0) ? v0 : ((d3 == 1) ? v1 : v2);
            *(float4*)(&sbuf[p][(1 * IMG_C + c) * SPITCH + (xq << 2)]) =
                lerp4(r1a, r1b, wy1);
        }

        // ---- advance rolling window to group g+1 ----
        if (g + 1 < NITER) {
            const int nrb   = tye0.x & 0xFFFF;
            const int shift = nrb - rb;       // 0..2, block-uniform
            const int valid = d3 - shift;     // highest still-valid idx
            d1  = (tye0.x >> 16) - nrb;
            d2  = (tye1.x & 0xFFFF) - nrb;
            d3  = (tye1.x >> 16) - nrb;
            wy0 = __int_as_float(tye0.y);
            wy1 = __int_as_float(tye1.y);

            if (shift == 1)      { v0 = v1; v1 = v2; }
            else if (shift == 2) { v0 = v2; }
            if (active) {
                if (valid < 0)            v0 = *(const float4*)(pc + (size_t)nrb * IMG_W);
                if (valid < 1 && d3 >= 1) v1 = *(const float4*)(pc + (size_t)(nrb + 1) * IMG_W);
                if (valid < 2 && d3 >= 2) v2 = *(const float4*)(pc + (size_t)(nrb + 2) * IMG_W);
            }
            rb = nrb;
        }

        __syncthreads();   // one barrier per group

        // ---- main: horizontal lerp, 2 LDS + 2 FFMA + 1 STG per output ----
        float* og = oblk + (size_t)(g * RPI) * IMG_W;
#pragma unroll
        for (int r = 0; r < RPI; r++) {
#pragma unroll
            for (int cc = 0; cc < IMG_C; cc++) {
                const float f0 = sbuf[p][(r * IMG_C + cc) * SPITCH + l0];
                const float f1 = sbuf[p][(r * IMG_C + cc) * SPITCH + l1];
                og[(size_t)cc * img_stride + (size_t)r * IMG_W] =
                    f0 + (f1 - f0) * wx;
            }
        }
    }
}

extern "C" void kernel_launch(void* const* d_in, const int* in_sizes, int n_in,
                              void* d_out, int out_size)
{
    const float* img = (const float*)d_in[0];
    const int*   y1  = (const int*)d_in[1];
    const int*   y2  = (const int*)d_in[2];
    const int*   x1  = (const int*)d_in[3];
    const int*   x2  = (const int*)d_in[4];
    float*       out = (float*)d_out;

    dim3 grid(IMG_H / NROWS, 64);   // (row chunk, b) = (32, 64)
    dim3 block(512);
    rand_crop_resize_kernel<<<grid, block>>>(img, y1, y2, x1, x2, out);
}